// round 7
// baseline (speedup 1.0000x reference)
#include <cuda_runtime.h>

// CrossAttMultiplexer collapses analytically:
//   out[n,i] = v[n,i] * sum_j softmax(...)[n,i,j] = s[n,i] * WV[0]
// Pure stream: read s (6.29MB), write out (6.29MB).
//
// R7: refine the R5 winner (only config to beat 6.85: 6.624us, with
// __ldcs/__stcs streaming hints). Keep the hints + front-batched 4x LDG.128,
// but tile exactly (384 CTAs x 256 thr x 4 float4 = 393,216) so the body is
// straight-line: no predicates, no loop (R5 paid 4% alu on bounds checks).

#define THREADS 256
#define BATCH   4

__global__ void __launch_bounds__(THREADS)
scale_stream_exact_kernel(const float4* __restrict__ s4,
                          const float* __restrict__ WV,
                          float4* __restrict__ out4) {
    const float wv = __ldg(WV);
    int base = blockIdx.x * (THREADS * BATCH) + threadIdx.x;

    float4 v[BATCH];
#pragma unroll
    for (int u = 0; u < BATCH; u++)
        v[u] = __ldcs(&s4[base + u * THREADS]);   // front-batched, evict-first
#pragma unroll
    for (int u = 0; u < BATCH; u++) {
        v[u].x *= wv; v[u].y *= wv; v[u].z *= wv; v[u].w *= wv;
        __stcs(&out4[base + u * THREADS], v[u]);  // streaming store
    }
}

// Generic fallback (bounds-checked, grid-stride) for sizes that don't tile.
__global__ void scale_generic_kernel(const float* __restrict__ s,
                                     const float* __restrict__ WV,
                                     float* __restrict__ out, int n) {
    const float wv = WV[0];
    for (int i = blockIdx.x * blockDim.x + threadIdx.x; i < n;
         i += gridDim.x * blockDim.x)
        out[i] = __ldcs(&s[i]) * wv;
}

extern "C" void kernel_launch(void* const* d_in, const int* in_sizes, int n_in,
                              void* d_out, int out_size) {
    // metadata order: x, s, WQ, WK, WV
    const float* s  = (const float*)d_in[1];
    const float* WV = (const float*)d_in[4];
    float* out = (float*)d_out;

    int n = out_size;                             // 1,572,864 expected
    const int tile = THREADS * BATCH * 4;         // 4096 elements per CTA
    if ((n % tile) == 0) {
        int blocks = n / tile;                    // 384
        scale_stream_exact_kernel<<<blocks, THREADS>>>((const float4*)s, WV,
                                                       (float4*)out);
    } else {
        int blocks = (n + 255) / 256;
        if (blocks > 1184) blocks = 1184;
        scale_generic_kernel<<<blocks, 256>>>(s, WV, out, n);
    }
}